// round 14
// baseline (speedup 1.0000x reference)
#include <cuda_runtime.h>
#include <cuda_bf16.h>
#include <math.h>
#include <stdint.h>

#define Bb 512
#define Tt 32
#define Dd 512
#define Mm 1024
#define Nn (Bb*Tt)

// ---------------- scratch ----------------
__device__ float g_sdA[(size_t)Nn * Mm];
__device__ float g_sdV[(size_t)Nn * Mm];
__device__ __nv_bfloat16 g_adjAh[(size_t)Nn * Mm];
__device__ __nv_bfloat16 g_LAh [(size_t)Nn * Mm];
__device__ __nv_bfloat16 g_adjVh[(size_t)Nn * Mm];
__device__ __nv_bfloat16 g_LVh [(size_t)Nn * Mm];
__device__ __nv_bfloat16 g_Ah[(size_t)Nn * Dd];
__device__ __nv_bfloat16 g_Vh[(size_t)Nn * Dd];
__device__ __nv_bfloat16 g_Eh[(size_t)Mm * Dd];
__device__ float g_xa[Nn];
__device__ float g_xv[Nn];
__device__ float g_en[Mm];
__device__ float g_pmax[2 * Tt * Bb * 4];
__device__ float g_psum[2 * Tt * Bb * 4];
__device__ float g_diag[2 * Tt * Bb];
__device__ unsigned g_minkey[2];
__device__ double g_acc;

// ---------------- helpers ----------------
__device__ __forceinline__ unsigned fenc(float f) {
    unsigned u = __float_as_uint(f);
    return (u & 0x80000000u) ? ~u : (u | 0x80000000u);
}
__device__ __forceinline__ float fdec(unsigned u) {
    return __uint_as_float((u & 0x80000000u) ? (u ^ 0x80000000u) : ~u);
}
__device__ __forceinline__ float warpRedSum(float v) {
    #pragma unroll
    for (int o = 16; o; o >>= 1) v += __shfl_down_sync(0xffffffffu, v, o);
    return v;
}
__device__ __forceinline__ float warpRedMin(float v) {
    #pragma unroll
    for (int o = 16; o; o >>= 1) v = fminf(v, __shfl_down_sync(0xffffffffu, v, o));
    return v;
}

__device__ __forceinline__ void cp16(uint32_t s, const void* g) {
    asm volatile("cp.async.cg.shared.global [%0], [%1], 16;"
                 :: "r"(s), "l"(__cvta_generic_to_global(g)) : "memory");
}
#define CP_COMMIT() asm volatile("cp.async.commit_group;" ::: "memory")
#define CP_WAIT2()  asm volatile("cp.async.wait_group 2;" ::: "memory")
#define CP_WAIT1()  asm volatile("cp.async.wait_group 1;" ::: "memory")
#define CP_WAIT0()  asm volatile("cp.async.wait_group 0;" ::: "memory")

#define LDSM4(r0, r1, r2, r3, a) \
    asm volatile("ldmatrix.sync.aligned.m8n8.x4.shared.b16 {%0,%1,%2,%3}, [%4];" \
                 : "=r"(r0), "=r"(r1), "=r"(r2), "=r"(r3) : "r"(a) : "memory")

#define MMA16816(c, a, b) \
    asm volatile("mma.sync.aligned.m16n8k16.row.col.f32.bf16.bf16.f32 " \
                 "{%0,%1,%2,%3}, {%4,%5,%6,%7}, {%8,%9}, {%0,%1,%2,%3};" \
                 : "+f"((c)[0]), "+f"((c)[1]), "+f"((c)[2]), "+f"((c)[3]) \
                 : "r"((a)[0]), "r"((a)[1]), "r"((a)[2]), "r"((a)[3]), \
                   "r"((b)[0]), "r"((b)[1]))

#define ROWB 80
#define A_B  (128 * ROWB)
#define STAGE (2 * 128 * ROWB)       // 20480
#define NSTG 4
#define DSM (NSTG * STAGE)           // 81920 -> 2 CTAs/SM (163840 <= 228KB)

__device__ __forceinline__ void issue_tile(
    uint32_t st, const __nv_bfloat16* __restrict__ Ag, const __nv_bfloat16* __restrict__ Bg,
    int ld, int k0, int tid)
{
    #pragma unroll
    for (int i = 0; i < 2; i++) {
        int ch = tid + i * 256;
        int row = ch >> 2, c4 = ch & 3;
        cp16(st + (uint32_t)row * ROWB + c4 * 16, Ag + (size_t)row * ld + k0 + c4 * 8);
        cp16(st + A_B + (uint32_t)row * ROWB + c4 * 16, Bg + (size_t)row * ld + k0 + c4 * 8);
    }
    CP_COMMIT();
}

__device__ __forceinline__ void compute_tile(
    uint32_t st, int wm, int wn, int lane, float acc[4][4][4])
{
    uint32_t sA = st, sB = st + A_B;
    #pragma unroll
    for (int s = 0; s < 2; s++) {
        uint32_t a[4][4];
        #pragma unroll
        for (int i = 0; i < 4; i++) {
            uint32_t addr = sA + (uint32_t)(wm * 64 + i * 16 + (lane & 15)) * ROWB
                          + s * 32 + (lane >> 4) * 16;
            LDSM4(a[i][0], a[i][1], a[i][2], a[i][3], addr);
        }
        uint32_t b[4][2];
        #pragma unroll
        for (int jj = 0; jj < 2; jj++) {
            uint32_t addr = sB + (uint32_t)(wn * 32 + jj * 16 + ((lane >> 4) * 8 + (lane & 7))) * ROWB
                          + ((lane >> 3) & 1) * 16 + s * 32;
            uint32_t r0, r1, r2, r3;
            LDSM4(r0, r1, r2, r3, addr);
            b[jj * 2][0] = r0;     b[jj * 2][1] = r1;
            b[jj * 2 + 1][0] = r2; b[jj * 2 + 1][1] = r3;
        }
        #pragma unroll
        for (int i = 0; i < 4; i++)
            #pragma unroll
            for (int j = 0; j < 4; j++)
                MMA16816(acc[i][j], a[i], b[j]);
    }
}

// 4-stage pipelined mainloop: prefetch 3 ahead, steady-state wait_group 2
__device__ __forceinline__ void hmma_mainloop(
    uint32_t sb, const __nv_bfloat16* __restrict__ Ag, const __nv_bfloat16* __restrict__ Bg,
    int ld, int NT, int tid, int wm, int wn, int lane, float acc[4][4][4])
{
    issue_tile(sb,             Ag, Bg, ld, 0,  tid);
    issue_tile(sb + STAGE,     Ag, Bg, ld, 32, tid);
    issue_tile(sb + 2 * STAGE, Ag, Bg, ld, 64, tid);
    for (int kt = 0; kt < NT; kt++) {
        int rem = NT - 1 - kt;               // younger groups still possibly pending
        if (rem >= 2) CP_WAIT2();
        else if (rem == 1) CP_WAIT1();
        else CP_WAIT0();
        __syncthreads();
        if (kt + 3 < NT)
            issue_tile(sb + ((kt + 3) & 3) * STAGE, Ag, Bg, ld, (kt + 3) * 32, tid);
        compute_tile(sb + (kt & 3) * STAGE, wm, wn, lane, acc);
    }
}

// ---------------- fused fp32->bf16 convert + row squared-norm (+ init) ----------------
__global__ __launch_bounds__(128) void k_cvt(
    const float* __restrict__ A, const float* __restrict__ V, const float* __restrict__ E)
{
    if (blockIdx.x == 0 && threadIdx.x == 0) {
        g_minkey[0] = 0xFFFFFFFFu;
        g_minkey[1] = 0xFFFFFFFFu;
        g_acc = 0.0;
    }
    int row = blockIdx.x;
    const float* src; __nv_bfloat16* dst; float* nrm; int r;
    if (row < Nn)          { src = A; dst = g_Ah; nrm = g_xa; r = row; }
    else if (row < 2 * Nn) { src = V; dst = g_Vh; nrm = g_xv; r = row - Nn; }
    else                   { src = E; dst = g_Eh; nrm = g_en; r = row - 2 * Nn; }

    int t = threadIdx.x;
    float4 v = *(const float4*)(src + (size_t)r * Dd + t * 4);
    float s = v.x * v.x + v.y * v.y + v.z * v.z + v.w * v.w;

    __nv_bfloat162 lo = __floats2bfloat162_rn(v.x, v.y);
    __nv_bfloat162 hi = __floats2bfloat162_rn(v.z, v.w);
    uint2 pk;
    pk.x = *(unsigned*)&lo;
    pk.y = *(unsigned*)&hi;
    *(uint2*)(dst + (size_t)r * Dd + t * 4) = pk;

    __shared__ float red[4];
    s = warpRedSum(s);
    int lane = t & 31, wid = t >> 5;
    if (lane == 0) red[wid] = s;
    __syncthreads();
    if (t == 0) nrm[r] = red[0] + red[1] + red[2] + red[3];
}

// ---------------- GEMM1 (HMMA 128x128): sd -> (T,B,M); which in blockIdx.z ----------------
__global__ __launch_bounds__(256, 2) void k_hmma_sd()
{
    extern __shared__ __align__(16) char sm[];
    uint32_t sb = (uint32_t)__cvta_generic_to_shared(sm);
    int tid = threadIdx.x, wid = tid >> 5, lane = tid & 31;
    int wm = wid & 1, wn = wid >> 1;
    int which = blockIdx.z;
    int m0 = blockIdx.x * 128, n0 = blockIdx.y * 128;

    const __nv_bfloat16* X = which ? g_Vh : g_Ah;
    const float* xn2 = which ? g_xv : g_xa;
    float* outsd = which ? g_sdV : g_sdA;

    float acc[4][4][4];
    #pragma unroll
    for (int i = 0; i < 4; i++)
        #pragma unroll
        for (int j = 0; j < 4; j++)
            #pragma unroll
            for (int c = 0; c < 4; c++) acc[i][j][c] = 0.f;

    hmma_mainloop(sb, X + (size_t)n0 * Dd, g_Eh + (size_t)m0 * Dd, Dd, Dd / 32,
                  tid, wm, wn, lane, acc);

    int g = lane >> 2, tg = lane & 3;
    #pragma unroll
    for (int i = 0; i < 4; i++) {
        int n_lo = n0 + wm * 64 + i * 16 + g;
        int n_hi = n_lo + 8;
        float xlo = xn2[n_lo], xhi = xn2[n_hi];
        float* rl = outsd + ((size_t)((n_lo & 31) * Bb + (n_lo >> 5))) * Mm;
        float* rh = outsd + ((size_t)((n_hi & 31) * Bb + (n_hi >> 5))) * Mm;
        #pragma unroll
        for (int j = 0; j < 4; j++) {
            int m = m0 + wn * 32 + j * 8 + tg * 2;
            float e0 = g_en[m], e1 = g_en[m + 1];
            float2 lo, hi;
            lo.x = sqrtf(fmaxf(fmaf(-2.f, acc[i][j][0], xlo + e0), 0.f));
            lo.y = sqrtf(fmaxf(fmaf(-2.f, acc[i][j][1], xlo + e1), 0.f));
            hi.x = sqrtf(fmaxf(fmaf(-2.f, acc[i][j][2], xhi + e0), 0.f));
            hi.y = sqrtf(fmaxf(fmaf(-2.f, acc[i][j][3], xhi + e1), 0.f));
            *(float2*)(rl + m) = lo;
            *(float2*)(rh + m) = hi;
        }
    }
}

// ---------------- softmax: one warp per row, single exp per element ----------------
__global__ __launch_bounds__(256) void k_softmax()
{
    int row = blockIdx.x * 8 + (threadIdx.x >> 5);
    int lane = threadIdx.x & 31;
    const float* sd; __nv_bfloat16 *adjh, *Lh;
    if (row < Nn) { sd = g_sdA; adjh = g_adjAh; Lh = g_LAh; }
    else          { sd = g_sdV; adjh = g_adjVh; Lh = g_LVh; row -= Nn; }

    size_t base = (size_t)row * Mm;
    float4 v[8];
    #pragma unroll
    for (int k = 0; k < 8; k++)
        v[k] = *(const float4*)(sd + base + ((size_t)(k * 32 + lane)) * 4);

    float mn = 3.402823466e38f;
    #pragma unroll
    for (int k = 0; k < 8; k++)
        mn = fminf(mn, fminf(fminf(v[k].x, v[k].y), fminf(v[k].z, v[k].w)));
    #pragma unroll
    for (int o = 16; o; o >>= 1) mn = fminf(mn, __shfl_xor_sync(0xffffffffu, mn, o));

    float4 e1[8];
    float s1 = 0.f, s2 = 0.f;
    #pragma unroll
    for (int k = 0; k < 8; k++) {
        e1[k].x = __expf(mn - v[k].x);
        e1[k].y = __expf(mn - v[k].y);
        e1[k].z = __expf(mn - v[k].z);
        e1[k].w = __expf(mn - v[k].w);
        s1 += e1[k].x + e1[k].y + e1[k].z + e1[k].w;
        s2 += e1[k].x * e1[k].x + e1[k].y * e1[k].y
            + e1[k].z * e1[k].z + e1[k].w * e1[k].w;
    }
    #pragma unroll
    for (int o = 16; o; o >>= 1) {
        s1 += __shfl_xor_sync(0xffffffffu, s1, o);
        s2 += __shfl_xor_sync(0xffffffffu, s2, o);
    }
    float inv2 = 1.f / s2;
    float c = mn - __logf(s1);

    #pragma unroll
    for (int k = 0; k < 8; k++) {
        size_t off = base + ((size_t)(k * 32 + lane)) * 4;
        __nv_bfloat162 a01 = __floats2bfloat162_rn(e1[k].x * e1[k].x * inv2,
                                                   e1[k].y * e1[k].y * inv2);
        __nv_bfloat162 a23 = __floats2bfloat162_rn(e1[k].z * e1[k].z * inv2,
                                                   e1[k].w * e1[k].w * inv2);
        __nv_bfloat162 l01 = __floats2bfloat162_rn(c - v[k].x, c - v[k].y);
        __nv_bfloat162 l23 = __floats2bfloat162_rn(c - v[k].z, c - v[k].w);
        uint2 pa, pl;
        pa.x = *(unsigned*)&a01; pa.y = *(unsigned*)&a23;
        pl.x = *(unsigned*)&l01; pl.y = *(unsigned*)&l23;
        *(uint2*)(adjh + off) = pa;
        *(uint2*)(Lh + off)   = pl;
    }
}

// ---------------- GEMM2 (HMMA 128x128): fused per-row partial logsumexp ----------------
__global__ __launch_bounds__(256, 2) void k_hmma_scode()
{
    extern __shared__ __align__(16) char sm[];
    uint32_t sb = (uint32_t)__cvta_generic_to_shared(sm);
    int tid = threadIdx.x, wid = tid >> 5, lane = tid & 31;
    int wm = wid & 1, wn = wid >> 1;
    int z = blockIdx.z;
    int which = z >= Tt;
    int t = z & (Tt - 1);
    int i0 = blockIdx.y * 128, j0 = blockIdx.x * 128;

    const __nv_bfloat16* Adj = which ? g_adjVh : g_adjAh;
    const __nv_bfloat16* Lm  = which ? g_LAh   : g_LVh;

    float acc[4][4][4];
    #pragma unroll
    for (int i = 0; i < 4; i++)
        #pragma unroll
        for (int j = 0; j < 4; j++)
            #pragma unroll
            for (int c = 0; c < 4; c++) acc[i][j][c] = 0.f;

    hmma_mainloop(sb,
                  Adj + ((size_t)t * Bb + i0) * Mm,
                  Lm  + ((size_t)t * Bb + j0) * Mm,
                  Mm, Mm / 32, tid, wm, wn, lane, acc);

    __syncthreads();
    float* sred = (float*)sm;              // [4][128]
    float* crm  = sred + 512;              // [128]

    int g = lane >> 2, tg = lane & 3;

    float thmin = 3.402823466e38f;
    #pragma unroll
    for (int i = 0; i < 4; i++) {
        float mx0 = -3.402823466e38f, mx1 = mx0;
        #pragma unroll
        for (int j = 0; j < 4; j++) {
            mx0 = fmaxf(mx0, fmaxf(acc[i][j][0], acc[i][j][1]));
            mx1 = fmaxf(mx1, fmaxf(acc[i][j][2], acc[i][j][3]));
            thmin = fminf(thmin, fminf(fminf(acc[i][j][0], acc[i][j][1]),
                                       fminf(acc[i][j][2], acc[i][j][3])));
        }
        #pragma unroll
        for (int o = 1; o <= 2; o <<= 1) {
            mx0 = fmaxf(mx0, __shfl_xor_sync(0xffffffffu, mx0, o));
            mx1 = fmaxf(mx1, __shfl_xor_sync(0xffffffffu, mx1, o));
        }
        if (tg == 0) {
            sred[wn * 128 + wm * 64 + i * 16 + g]     = mx0;
            sred[wn * 128 + wm * 64 + i * 16 + g + 8] = mx1;
        }
    }
    __syncthreads();
    if (tid < 128)
        crm[tid] = fmaxf(fmaxf(sred[tid], sred[128 + tid]),
                         fmaxf(sred[256 + tid], sred[384 + tid]));
    __syncthreads();

    #pragma unroll
    for (int i = 0; i < 4; i++) {
        int lr0 = wm * 64 + i * 16 + g;
        int lr1 = lr0 + 8;
        float cm0 = crm[lr0], cm1 = crm[lr1];
        int gr0 = i0 + lr0, gr1 = i0 + lr1;
        float s0 = 0.f, s1 = 0.f;
        #pragma unroll
        for (int j = 0; j < 4; j++) {
            int c = j0 + wn * 32 + j * 8 + tg * 2;
            s0 += __expf(acc[i][j][0] - cm0) + __expf(acc[i][j][1] - cm0);
            s1 += __expf(acc[i][j][2] - cm1) + __expf(acc[i][j][3] - cm1);
            if (c == gr0)     g_diag[(which * Tt + t) * Bb + gr0] = acc[i][j][0];
            if (c + 1 == gr0) g_diag[(which * Tt + t) * Bb + gr0] = acc[i][j][1];
            if (c == gr1)     g_diag[(which * Tt + t) * Bb + gr1] = acc[i][j][2];
            if (c + 1 == gr1) g_diag[(which * Tt + t) * Bb + gr1] = acc[i][j][3];
        }
        #pragma unroll
        for (int o = 1; o <= 2; o <<= 1) {
            s0 += __shfl_xor_sync(0xffffffffu, s0, o);
            s1 += __shfl_xor_sync(0xffffffffu, s1, o);
        }
        if (tg == 0) {
            sred[wn * 128 + lr0] = s0;
            sred[wn * 128 + lr1] = s1;
        }
    }
    __syncthreads();
    if (tid < 128) {
        float s = sred[tid] + sred[128 + tid] + sred[256 + tid] + sred[384 + tid];
        size_t p = (size_t)(((which * Tt + t) * Bb + i0 + tid)) * 4 + (j0 >> 7);
        g_pmax[p] = crm[tid];
        g_psum[p] = s;
    }

    __shared__ float redm[8];
    thmin = warpRedMin(thmin);
    if (lane == 0) redm[wid] = thmin;
    __syncthreads();
    if (tid == 0) {
        float m = redm[0];
        #pragma unroll
        for (int w = 1; w < 8; w++) m = fminf(m, redm[w]);
        atomicMin(&g_minkey[which], fenc(m));
    }
}

// ---------------- final loss ----------------
__global__ __launch_bounds__(256) void k_loss()
{
    int idx = blockIdx.x * 256 + threadIdx.x;
    int w = idx >> 14;
    int r = idx & 16383;
    float mn = fdec(g_minkey[w]);
    size_t p = ((size_t)(w * 16384 + r)) * 4;
    double denom = 0.0;
    #pragma unroll
    for (int q = 0; q < 4; q++)
        denom += exp((double)(g_pmax[p + q] - mn)) * (double)g_psum[p + q];
    double term = log(denom + 1e-5) - (double)(g_diag[w * 16384 + r] - mn);

    __shared__ double red[8];
    #pragma unroll
    for (int o = 16; o; o >>= 1) term += __shfl_down_sync(0xffffffffu, term, o);
    int lane = threadIdx.x & 31, wid = threadIdx.x >> 5;
    if (lane == 0) red[wid] = term;
    __syncthreads();
    if (threadIdx.x == 0) {
        double s = 0.0;
        #pragma unroll
        for (int ww = 0; ww < 8; ww++) s += red[ww];
        atomicAdd(&g_acc, s);
    }
}

__global__ void k_final(float* out) {
    out[0] = (float)(g_acc * (1.0 / (2.0 * Tt * Bb)));
}

// ---------------- launch ----------------
extern "C" void kernel_launch(void* const* d_in, const int* in_sizes, int n_in,
                              void* d_out, int out_size)
{
    const float* A = (const float*)d_in[0];
    const float* V = (const float*)d_in[1];
    const float* E = (const float*)d_in[2];
    float* out = (float*)d_out;

    static bool inited = false;
    if (!inited) {
        inited = true;
        cudaFuncSetAttribute(k_hmma_sd,    cudaFuncAttributeMaxDynamicSharedMemorySize, DSM);
        cudaFuncSetAttribute(k_hmma_scode, cudaFuncAttributeMaxDynamicSharedMemorySize, DSM);
    }

    k_cvt<<<2 * Nn + Mm, 128>>>(A, V, E);

    dim3 g1(Mm / 128, Nn / 128, 2);
    k_hmma_sd<<<g1, 256, DSM>>>();

    k_softmax<<<(2 * Nn) / 8, 256>>>();

    dim3 g2(Bb / 128, Bb / 128, 2 * Tt);
    k_hmma_scode<<<g2, 256, DSM>>>();

    k_loss<<<(2 * Tt * Bb) / 256, 256>>>();
    k_final<<<1, 1>>>(out);
}

// round 16
// speedup vs baseline: 1.0760x; 1.0760x over previous
#include <cuda_runtime.h>
#include <cuda_bf16.h>
#include <math.h>
#include <stdint.h>

#define Bb 512
#define Tt 32
#define Dd 512
#define Mm 1024
#define Nn (Bb*Tt)

// ---------------- scratch ----------------
__device__ float g_sdA[(size_t)Nn * Mm];
__device__ float g_sdV[(size_t)Nn * Mm];
__device__ __nv_bfloat16 g_adjAh[(size_t)Nn * Mm];
__device__ __nv_bfloat16 g_LAh [(size_t)Nn * Mm];
__device__ __nv_bfloat16 g_adjVh[(size_t)Nn * Mm];
__device__ __nv_bfloat16 g_LVh [(size_t)Nn * Mm];
__device__ __nv_bfloat16 g_Ah[(size_t)Nn * Dd];
__device__ __nv_bfloat16 g_Vh[(size_t)Nn * Dd];
__device__ __nv_bfloat16 g_Eh[(size_t)Mm * Dd];
__device__ float g_xa[Nn];
__device__ float g_xv[Nn];
__device__ float g_en[Mm];
__device__ float g_pmax[2 * Tt * Bb * 4];
__device__ float g_psum[2 * Tt * Bb * 4];
__device__ float g_diag[2 * Tt * Bb];
__device__ unsigned g_minkey[2];
__device__ double g_acc;

// ---------------- helpers ----------------
__device__ __forceinline__ unsigned fenc(float f) {
    unsigned u = __float_as_uint(f);
    return (u & 0x80000000u) ? ~u : (u | 0x80000000u);
}
__device__ __forceinline__ float fdec(unsigned u) {
    return __uint_as_float((u & 0x80000000u) ? (u ^ 0x80000000u) : ~u);
}
__device__ __forceinline__ float warpRedSum(float v) {
    #pragma unroll
    for (int o = 16; o; o >>= 1) v += __shfl_down_sync(0xffffffffu, v, o);
    return v;
}
__device__ __forceinline__ float warpRedMin(float v) {
    #pragma unroll
    for (int o = 16; o; o >>= 1) v = fminf(v, __shfl_down_sync(0xffffffffu, v, o));
    return v;
}

__device__ __forceinline__ void cp16(uint32_t s, const void* g) {
    asm volatile("cp.async.cg.shared.global [%0], [%1], 16;"
                 :: "r"(s), "l"(__cvta_generic_to_global(g)) : "memory");
}
#define CP_COMMIT() asm volatile("cp.async.commit_group;" ::: "memory")
#define CP_WAIT1()  asm volatile("cp.async.wait_group 1;" ::: "memory")
#define CP_WAIT0()  asm volatile("cp.async.wait_group 0;" ::: "memory")

#define LDSM4(r0, r1, r2, r3, a) \
    asm volatile("ldmatrix.sync.aligned.m8n8.x4.shared.b16 {%0,%1,%2,%3}, [%4];" \
                 : "=r"(r0), "=r"(r1), "=r"(r2), "=r"(r3) : "r"(a) : "memory")

#define MMA16816(c, a, b) \
    asm volatile("mma.sync.aligned.m16n8k16.row.col.f32.bf16.bf16.f32 " \
                 "{%0,%1,%2,%3}, {%4,%5,%6,%7}, {%8,%9}, {%0,%1,%2,%3};" \
                 : "+f"((c)[0]), "+f"((c)[1]), "+f"((c)[2]), "+f"((c)[3]) \
                 : "r"((a)[0]), "r"((a)[1]), "r"((a)[2]), "r"((a)[3]), \
                   "r"((b)[0]), "r"((b)[1]))

#define ROWB 80
#define A_B  (128 * ROWB)
#define STAGE (2 * 128 * ROWB)       // 20480
#define NSTG 3
#define DSM (NSTG * STAGE)           // 61440 -> 2 CTAs/SM, preserves L1 carve-out

__device__ __forceinline__ void issue_tile(
    uint32_t st, const __nv_bfloat16* __restrict__ Ag, const __nv_bfloat16* __restrict__ Bg,
    int ld, int k0, int tid)
{
    #pragma unroll
    for (int i = 0; i < 2; i++) {
        int ch = tid + i * 256;
        int row = ch >> 2, c4 = ch & 3;
        cp16(st + (uint32_t)row * ROWB + c4 * 16, Ag + (size_t)row * ld + k0 + c4 * 8);
        cp16(st + A_B + (uint32_t)row * ROWB + c4 * 16, Bg + (size_t)row * ld + k0 + c4 * 8);
    }
    CP_COMMIT();
}

__device__ __forceinline__ void compute_tile(
    uint32_t st, int wm, int wn, int lane, float acc[4][4][4])
{
    uint32_t sA = st, sB = st + A_B;
    #pragma unroll
    for (int s = 0; s < 2; s++) {
        uint32_t a[4][4];
        #pragma unroll
        for (int i = 0; i < 4; i++) {
            uint32_t addr = sA + (uint32_t)(wm * 64 + i * 16 + (lane & 15)) * ROWB
                          + s * 32 + (lane >> 4) * 16;
            LDSM4(a[i][0], a[i][1], a[i][2], a[i][3], addr);
        }
        uint32_t b[4][2];
        #pragma unroll
        for (int jj = 0; jj < 2; jj++) {
            uint32_t addr = sB + (uint32_t)(wn * 32 + jj * 16 + ((lane >> 4) * 8 + (lane & 7))) * ROWB
                          + ((lane >> 3) & 1) * 16 + s * 32;
            uint32_t r0, r1, r2, r3;
            LDSM4(r0, r1, r2, r3, addr);
            b[jj * 2][0] = r0;     b[jj * 2][1] = r1;
            b[jj * 2 + 1][0] = r2; b[jj * 2 + 1][1] = r3;
        }
        #pragma unroll
        for (int i = 0; i < 4; i++)
            #pragma unroll
            for (int j = 0; j < 4; j++)
                MMA16816(acc[i][j], a[i], b[j]);
    }
}

// 3-stage pipelined mainloop, one __syncthreads per k-tile (proven R11 config)
__device__ __forceinline__ void hmma_mainloop(
    uint32_t sb, const __nv_bfloat16* __restrict__ Ag, const __nv_bfloat16* __restrict__ Bg,
    int ld, int NT, int tid, int wm, int wn, int lane, float acc[4][4][4])
{
    issue_tile(sb, Ag, Bg, ld, 0, tid);
    issue_tile(sb + STAGE, Ag, Bg, ld, 32, tid);
    for (int kt = 0; kt < NT; kt++) {
        if (kt + 1 < NT) CP_WAIT1(); else CP_WAIT0();
        __syncthreads();
        if (kt + 2 < NT)
            issue_tile(sb + ((kt + 2) % 3) * STAGE, Ag, Bg, ld, (kt + 2) * 32, tid);
        compute_tile(sb + (kt % 3) * STAGE, wm, wn, lane, acc);
    }
}

// ---------------- fused fp32->bf16 convert + row squared-norm (+ init) ----------------
__global__ __launch_bounds__(128) void k_cvt(
    const float* __restrict__ A, const float* __restrict__ V, const float* __restrict__ E)
{
    if (blockIdx.x == 0 && threadIdx.x == 0) {
        g_minkey[0] = 0xFFFFFFFFu;
        g_minkey[1] = 0xFFFFFFFFu;
        g_acc = 0.0;
    }
    int row = blockIdx.x;
    const float* src; __nv_bfloat16* dst; float* nrm; int r;
    if (row < Nn)          { src = A; dst = g_Ah; nrm = g_xa; r = row; }
    else if (row < 2 * Nn) { src = V; dst = g_Vh; nrm = g_xv; r = row - Nn; }
    else                   { src = E; dst = g_Eh; nrm = g_en; r = row - 2 * Nn; }

    int t = threadIdx.x;
    float4 v = *(const float4*)(src + (size_t)r * Dd + t * 4);
    float s = v.x * v.x + v.y * v.y + v.z * v.z + v.w * v.w;

    __nv_bfloat162 lo = __floats2bfloat162_rn(v.x, v.y);
    __nv_bfloat162 hi = __floats2bfloat162_rn(v.z, v.w);
    uint2 pk;
    pk.x = *(unsigned*)&lo;
    pk.y = *(unsigned*)&hi;
    *(uint2*)(dst + (size_t)r * Dd + t * 4) = pk;

    __shared__ float red[4];
    s = warpRedSum(s);
    int lane = t & 31, wid = t >> 5;
    if (lane == 0) red[wid] = s;
    __syncthreads();
    if (t == 0) nrm[r] = red[0] + red[1] + red[2] + red[3];
}

// ---------------- GEMM1 (HMMA 128x128): sd -> (T,B,M); which in blockIdx.z ----------------
__global__ __launch_bounds__(256, 2) void k_hmma_sd()
{
    extern __shared__ __align__(16) char sm[];
    uint32_t sb = (uint32_t)__cvta_generic_to_shared(sm);
    int tid = threadIdx.x, wid = tid >> 5, lane = tid & 31;
    int wm = wid & 1, wn = wid >> 1;
    int which = blockIdx.z;
    int m0 = blockIdx.x * 128, n0 = blockIdx.y * 128;

    const __nv_bfloat16* X = which ? g_Vh : g_Ah;
    const float* xn2 = which ? g_xv : g_xa;
    float* outsd = which ? g_sdV : g_sdA;

    float acc[4][4][4];
    #pragma unroll
    for (int i = 0; i < 4; i++)
        #pragma unroll
        for (int j = 0; j < 4; j++)
            #pragma unroll
            for (int c = 0; c < 4; c++) acc[i][j][c] = 0.f;

    hmma_mainloop(sb, X + (size_t)n0 * Dd, g_Eh + (size_t)m0 * Dd, Dd, Dd / 32,
                  tid, wm, wn, lane, acc);

    int g = lane >> 2, tg = lane & 3;
    #pragma unroll
    for (int i = 0; i < 4; i++) {
        int n_lo = n0 + wm * 64 + i * 16 + g;
        int n_hi = n_lo + 8;
        float xlo = xn2[n_lo], xhi = xn2[n_hi];
        float* rl = outsd + ((size_t)((n_lo & 31) * Bb + (n_lo >> 5))) * Mm;
        float* rh = outsd + ((size_t)((n_hi & 31) * Bb + (n_hi >> 5))) * Mm;
        #pragma unroll
        for (int j = 0; j < 4; j++) {
            int m = m0 + wn * 32 + j * 8 + tg * 2;
            float e0 = g_en[m], e1 = g_en[m + 1];
            float2 lo, hi;
            lo.x = sqrtf(fmaxf(fmaf(-2.f, acc[i][j][0], xlo + e0), 0.f));
            lo.y = sqrtf(fmaxf(fmaf(-2.f, acc[i][j][1], xlo + e1), 0.f));
            hi.x = sqrtf(fmaxf(fmaf(-2.f, acc[i][j][2], xhi + e0), 0.f));
            hi.y = sqrtf(fmaxf(fmaf(-2.f, acc[i][j][3], xhi + e1), 0.f));
            *(float2*)(rl + m) = lo;
            *(float2*)(rh + m) = hi;
        }
    }
}

// ---------------- softmax: one warp per row, single exp per element ----------------
__global__ __launch_bounds__(256) void k_softmax()
{
    int row = blockIdx.x * 8 + (threadIdx.x >> 5);
    int lane = threadIdx.x & 31;
    const float* sd; __nv_bfloat16 *adjh, *Lh;
    if (row < Nn) { sd = g_sdA; adjh = g_adjAh; Lh = g_LAh; }
    else          { sd = g_sdV; adjh = g_adjVh; Lh = g_LVh; row -= Nn; }

    size_t base = (size_t)row * Mm;
    float4 v[8];
    #pragma unroll
    for (int k = 0; k < 8; k++)
        v[k] = *(const float4*)(sd + base + ((size_t)(k * 32 + lane)) * 4);

    float mn = 3.402823466e38f;
    #pragma unroll
    for (int k = 0; k < 8; k++)
        mn = fminf(mn, fminf(fminf(v[k].x, v[k].y), fminf(v[k].z, v[k].w)));
    #pragma unroll
    for (int o = 16; o; o >>= 1) mn = fminf(mn, __shfl_xor_sync(0xffffffffu, mn, o));

    float4 e1[8];
    float s1 = 0.f, s2 = 0.f;
    #pragma unroll
    for (int k = 0; k < 8; k++) {
        e1[k].x = __expf(mn - v[k].x);
        e1[k].y = __expf(mn - v[k].y);
        e1[k].z = __expf(mn - v[k].z);
        e1[k].w = __expf(mn - v[k].w);
        s1 += e1[k].x + e1[k].y + e1[k].z + e1[k].w;
        s2 += e1[k].x * e1[k].x + e1[k].y * e1[k].y
            + e1[k].z * e1[k].z + e1[k].w * e1[k].w;
    }
    #pragma unroll
    for (int o = 16; o; o >>= 1) {
        s1 += __shfl_xor_sync(0xffffffffu, s1, o);
        s2 += __shfl_xor_sync(0xffffffffu, s2, o);
    }
    float inv2 = 1.f / s2;
    float c = mn - __logf(s1);

    #pragma unroll
    for (int k = 0; k < 8; k++) {
        size_t off = base + ((size_t)(k * 32 + lane)) * 4;
        __nv_bfloat162 a01 = __floats2bfloat162_rn(e1[k].x * e1[k].x * inv2,
                                                   e1[k].y * e1[k].y * inv2);
        __nv_bfloat162 a23 = __floats2bfloat162_rn(e1[k].z * e1[k].z * inv2,
                                                   e1[k].w * e1[k].w * inv2);
        __nv_bfloat162 l01 = __floats2bfloat162_rn(c - v[k].x, c - v[k].y);
        __nv_bfloat162 l23 = __floats2bfloat162_rn(c - v[k].z, c - v[k].w);
        uint2 pa, pl;
        pa.x = *(unsigned*)&a01; pa.y = *(unsigned*)&a23;
        pl.x = *(unsigned*)&l01; pl.y = *(unsigned*)&l23;
        *(uint2*)(adjh + off) = pa;
        *(uint2*)(Lh + off)   = pl;
    }
}

// ---------------- GEMM2 (HMMA 128x128): fused per-row partial logsumexp ----------------
__global__ __launch_bounds__(256, 2) void k_hmma_scode()
{
    extern __shared__ __align__(16) char sm[];
    uint32_t sb = (uint32_t)__cvta_generic_to_shared(sm);
    int tid = threadIdx.x, wid = tid >> 5, lane = tid & 31;
    int wm = wid & 1, wn = wid >> 1;
    int z = blockIdx.z;
    int which = z >= Tt;
    int t = z & (Tt - 1);
    int i0 = blockIdx.y * 128, j0 = blockIdx.x * 128;

    const __nv_bfloat16* Adj = which ? g_adjVh : g_adjAh;
    const __nv_bfloat16* Lm  = which ? g_LAh   : g_LVh;

    float acc[4][4][4];
    #pragma unroll
    for (int i = 0; i < 4; i++)
        #pragma unroll
        for (int j = 0; j < 4; j++)
            #pragma unroll
            for (int c = 0; c < 4; c++) acc[i][j][c] = 0.f;

    hmma_mainloop(sb,
                  Adj + ((size_t)t * Bb + i0) * Mm,
                  Lm  + ((size_t)t * Bb + j0) * Mm,
                  Mm, Mm / 32, tid, wm, wn, lane, acc);

    __syncthreads();
    float* sred = (float*)sm;              // [4][128]
    float* crm  = sred + 512;              // [128]

    int g = lane >> 2, tg = lane & 3;

    float thmin = 3.402823466e38f;
    #pragma unroll
    for (int i = 0; i < 4; i++) {
        float mx0 = -3.402823466e38f, mx1 = mx0;
        #pragma unroll
        for (int j = 0; j < 4; j++) {
            mx0 = fmaxf(mx0, fmaxf(acc[i][j][0], acc[i][j][1]));
            mx1 = fmaxf(mx1, fmaxf(acc[i][j][2], acc[i][j][3]));
            thmin = fminf(thmin, fminf(fminf(acc[i][j][0], acc[i][j][1]),
                                       fminf(acc[i][j][2], acc[i][j][3])));
        }
        #pragma unroll
        for (int o = 1; o <= 2; o <<= 1) {
            mx0 = fmaxf(mx0, __shfl_xor_sync(0xffffffffu, mx0, o));
            mx1 = fmaxf(mx1, __shfl_xor_sync(0xffffffffu, mx1, o));
        }
        if (tg == 0) {
            sred[wn * 128 + wm * 64 + i * 16 + g]     = mx0;
            sred[wn * 128 + wm * 64 + i * 16 + g + 8] = mx1;
        }
    }
    __syncthreads();
    if (tid < 128)
        crm[tid] = fmaxf(fmaxf(sred[tid], sred[128 + tid]),
                         fmaxf(sred[256 + tid], sred[384 + tid]));
    __syncthreads();

    #pragma unroll
    for (int i = 0; i < 4; i++) {
        int lr0 = wm * 64 + i * 16 + g;
        int lr1 = lr0 + 8;
        float cm0 = crm[lr0], cm1 = crm[lr1];
        int gr0 = i0 + lr0, gr1 = i0 + lr1;
        float s0 = 0.f, s1 = 0.f;
        #pragma unroll
        for (int j = 0; j < 4; j++) {
            int c = j0 + wn * 32 + j * 8 + tg * 2;
            s0 += __expf(acc[i][j][0] - cm0) + __expf(acc[i][j][1] - cm0);
            s1 += __expf(acc[i][j][2] - cm1) + __expf(acc[i][j][3] - cm1);
            if (c == gr0)     g_diag[(which * Tt + t) * Bb + gr0] = acc[i][j][0];
            if (c + 1 == gr0) g_diag[(which * Tt + t) * Bb + gr0] = acc[i][j][1];
            if (c == gr1)     g_diag[(which * Tt + t) * Bb + gr1] = acc[i][j][2];
            if (c + 1 == gr1) g_diag[(which * Tt + t) * Bb + gr1] = acc[i][j][3];
        }
        #pragma unroll
        for (int o = 1; o <= 2; o <<= 1) {
            s0 += __shfl_xor_sync(0xffffffffu, s0, o);
            s1 += __shfl_xor_sync(0xffffffffu, s1, o);
        }
        if (tg == 0) {
            sred[wn * 128 + lr0] = s0;
            sred[wn * 128 + lr1] = s1;
        }
    }
    __syncthreads();
    if (tid < 128) {
        float s = sred[tid] + sred[128 + tid] + sred[256 + tid] + sred[384 + tid];
        size_t p = (size_t)(((which * Tt + t) * Bb + i0 + tid)) * 4 + (j0 >> 7);
        g_pmax[p] = crm[tid];
        g_psum[p] = s;
    }

    __shared__ float redm[8];
    thmin = warpRedMin(thmin);
    if (lane == 0) redm[wid] = thmin;
    __syncthreads();
    if (tid == 0) {
        float m = redm[0];
        #pragma unroll
        for (int w = 1; w < 8; w++) m = fminf(m, redm[w]);
        atomicMin(&g_minkey[which], fenc(m));
    }
}

// ---------------- final loss ----------------
__global__ __launch_bounds__(256) void k_loss()
{
    int idx = blockIdx.x * 256 + threadIdx.x;
    int w = idx >> 14;
    int r = idx & 16383;
    float mn = fdec(g_minkey[w]);
    size_t p = ((size_t)(w * 16384 + r)) * 4;
    double denom = 0.0;
    #pragma unroll
    for (int q = 0; q < 4; q++)
        denom += exp((double)(g_pmax[p + q] - mn)) * (double)g_psum[p + q];
    double term = log(denom + 1e-5) - (double)(g_diag[w * 16384 + r] - mn);

    __shared__ double red[8];
    #pragma unroll
    for (int o = 16; o; o >>= 1) term += __shfl_down_sync(0xffffffffu, term, o);
    int lane = threadIdx.x & 31, wid = threadIdx.x >> 5;
    if (lane == 0) red[wid] = term;
    __syncthreads();
    if (threadIdx.x == 0) {
        double s = 0.0;
        #pragma unroll
        for (int ww = 0; ww < 8; ww++) s += red[ww];
        atomicAdd(&g_acc, s);
    }
}

__global__ void k_final(float* out) {
    out[0] = (float)(g_acc * (1.0 / (2.0 * Tt * Bb)));
}

// ---------------- launch ----------------
extern "C" void kernel_launch(void* const* d_in, const int* in_sizes, int n_in,
                              void* d_out, int out_size)
{
    const float* A = (const float*)d_in[0];
    const float* V = (const float*)d_in[1];
    const float* E = (const float*)d_in[2];
    float* out = (float*)d_out;

    static bool inited = false;
    if (!inited) {
        inited = true;
        cudaFuncSetAttribute(k_hmma_sd,    cudaFuncAttributeMaxDynamicSharedMemorySize, DSM);
        cudaFuncSetAttribute(k_hmma_scode, cudaFuncAttributeMaxDynamicSharedMemorySize, DSM);
    }

    k_cvt<<<2 * Nn + Mm, 128>>>(A, V, E);

    dim3 g1(Mm / 128, Nn / 128, 2);
    k_hmma_sd<<<g1, 256, DSM>>>();

    k_softmax<<<(2 * Nn) / 8, 256>>>();

    dim3 g2(Bb / 128, Bb / 128, 2 * Tt);
    k_hmma_scode<<<g2, 256, DSM>>>();

    k_loss<<<(2 * Tt * Bb) / 256, 256>>>();
    k_final<<<1, 1>>>(out);
}